// round 3
// baseline (speedup 1.0000x reference)
#include <cuda_runtime.h>

// Problem constants
#define BB 256
#define TT 1024
#define VV 6
#define DD 64
#define UU 64
#define GG 256   // 4*U gate columns

// Precomputed per-vocab tables (V=6): xproj rows and mask bits.
__device__ float g_xprojF[VV][GG];
__device__ float g_xprojB[VV][GG];
__device__ int   g_maskv[VV];

__device__ __forceinline__ float sigmoid_fast(float x) {
    return __fdividef(1.f, 1.f + __expf(-x));
}
__device__ __forceinline__ float tanh_fast(float x) {
    return 2.f * __fdividef(1.f, 1.f + __expf(-2.f * x)) - 1.f;
}

__device__ __forceinline__ unsigned long long pack2(float lo, float hi) {
    unsigned long long r;
    asm("mov.b64 %0, {%1, %2};" : "=l"(r) : "f"(lo), "f"(hi));
    return r;
}
__device__ __forceinline__ void unpack2(unsigned long long v, float& lo, float& hi) {
    asm("mov.b64 {%0, %1}, %2;" : "=f"(lo), "=f"(hi) : "l"(v));
}
// Packed dual-FMA (sm_10x FFMA2 path; only reachable via PTX f32x2)
#define FMA2(d, a, b, c) \
    asm("fma.rn.f32x2 %0, %1, %2, %3;" : "=l"(d) : "l"(a), "l"(b), "l"(c))
#define ADD2(d, a, b) \
    asm("add.rn.f32x2 %0, %1, %2;" : "=l"(d) : "l"(a), "l"(b))

// Precompute: xprojF[v][g] = emb[v] . Wk_f[:,g] + b_f[g]; same for backward;
// mask_v[v] = any(emb[v] != 0).
__global__ void precompute_kernel(const float* __restrict__ emb,
                                  const float* __restrict__ Wk_f,
                                  const float* __restrict__ b_f,
                                  const float* __restrict__ Wk_b,
                                  const float* __restrict__ b_b) {
    int v = blockIdx.x;
    int g = threadIdx.x;
    float sf = 0.f, sb = 0.f;
    #pragma unroll 8
    for (int k = 0; k < DD; k++) {
        float e = emb[v * DD + k];
        sf = fmaf(e, Wk_f[k * GG + g], sf);
        sb = fmaf(e, Wk_b[k * GG + g], sb);
    }
    g_xprojF[v][g] = sf + b_f[g];
    g_xprojB[v][g] = sb + b_b[g];
    if (g == 0) {
        int m = 0;
        for (int k = 0; k < DD; k++) m |= (emb[v * DD + k] != 0.f);
        g_maskv[v] = m;
    }
}

// One CTA per PAIR of batch elements (grid = 128 -> single balanced wave on
// 148 SMs). 256 threads; thread t owns gate column col = gi*64+u for BOTH
// batches via fma.rn.f32x2 (packed {b0, b1}). Wr_f column weights held as
// duplicated b64 pairs in registers (128 regs). h double-buffered in smem as
// float2 {h_b0, h_b1}; one __syncthreads per step.
__global__ void __launch_bounds__(256, 1)
lstm_fwd2_kernel(const int* __restrict__ tokens,
                 const float* __restrict__ Wr_f,
                 const float* __restrict__ Wd,
                 const float* __restrict__ bd,
                 float* __restrict__ out) {
    __shared__ float sh_xF[VV * GG];                 // 6 KB
    __shared__ int2  sh_tok[TT];                     // 8 KB {tok_b0, tok_b1}
    __shared__ __align__(16) float2 sh_h[2][UU];     // double-buffered h pairs
    __shared__ int   sh_mask[VV];
    __shared__ float sh_red[4];

    const int bp   = blockIdx.x;
    const int b0   = 2 * bp, b1 = 2 * bp + 1;
    const int t    = threadIdx.x;
    const int u    = t >> 2;
    const int gi   = t & 3;
    const int col  = gi * UU + u;
    const int lane = t & 31;
    const int qb   = lane & ~3;          // quad base lane

    // Recurrent weight column, duplicated into both packed halves.
    unsigned long long w2[UU];
    #pragma unroll
    for (int k = 0; k < UU; k++) {
        float w = Wr_f[k * GG + col];
        w2[k] = pack2(w, w);
    }

    // Stage tokens (interleaved pair) + tables into smem.
    for (int i = t; i < TT; i += 256)
        sh_tok[i] = make_int2(tokens[b0 * TT + i], tokens[b1 * TT + i]);
    for (int i = t; i < VV * GG; i += 256) sh_xF[i] = (&g_xprojF[0][0])[i];
    if (t < VV) sh_mask[t] = g_maskv[t];
    if (t < UU) { sh_h[0][t] = make_float2(0.f, 0.f); sh_h[1][t] = make_float2(0.f, 0.f); }
    __syncthreads();

    float cx = 0.f, cy = 0.f;   // cell state pair, live only in gi==3 lanes

    for (int s = 0; s < TT; s++) {
        const float2* __restrict__ hr = sh_h[s & 1];
        float2*       __restrict__ hw = sh_h[(s + 1) & 1];

        const int2 tk = sh_tok[s];
        // Seed accumulator 0 with the xproj pair (different token per batch).
        unsigned long long acc0 = pack2(sh_xF[tk.x * GG + col],
                                        sh_xF[tk.y * GG + col]);
        unsigned long long acc1 = 0ull, acc2 = 0ull, acc3 = 0ull;

        // z += h . Wr[:, col] for both batches at once; 4 independent chains.
        #pragma unroll
        for (int k = 0; k < UU; k += 4) {
            // float2 pairs {k,k+1} and {k+2,k+3}; bit-identical to packed b64.
            ulonglong2 p0 = *reinterpret_cast<const ulonglong2*>(&hr[k]);
            ulonglong2 p1 = *reinterpret_cast<const ulonglong2*>(&hr[k + 2]);
            FMA2(acc0, p0.x, w2[k + 0], acc0);
            FMA2(acc1, p0.y, w2[k + 1], acc1);
            FMA2(acc2, p1.x, w2[k + 2], acc2);
            FMA2(acc3, p1.y, w2[k + 3], acc3);
        }
        ADD2(acc0, acc0, acc1);
        ADD2(acc2, acc2, acc3);
        ADD2(acc0, acc0, acc2);

        float zx, zy;
        unpack2(acc0, zx, zy);

        // Activation: gi==2 is the g-gate (tanh), others sigmoid.
        float ax, ay;
        if (gi == 2) { ax = tanh_fast(zx);    ay = tanh_fast(zy);    }
        else         { ax = sigmoid_fast(zx); ay = sigmoid_fast(zy); }

        // Gather i,f,g into the o-lane (gi==3) via intra-quad shuffles (both halves).
        float vix = __shfl_sync(0xffffffffu, ax, qb + 0);
        float viy = __shfl_sync(0xffffffffu, ay, qb + 0);
        float vfx = __shfl_sync(0xffffffffu, ax, qb + 1);
        float vfy = __shfl_sync(0xffffffffu, ay, qb + 1);
        float vgx = __shfl_sync(0xffffffffu, ax, qb + 2);
        float vgy = __shfl_sync(0xffffffffu, ay, qb + 2);

        if (gi == 3) {
            float cnx = fmaf(vfx, cx, vix * vgx);
            float cny = fmaf(vfy, cy, viy * vgy);
            float hnx = ax * tanh_fast(cnx);
            float hny = ay * tanh_fast(cny);
            const int m0 = sh_mask[tk.x];
            const int m1 = sh_mask[tk.y];
            float2 ho = hr[u];
            cx = m0 ? cnx : cx;
            cy = m1 ? cny : cy;
            hw[u] = make_float2(m0 ? hnx : ho.x, m1 ? hny : ho.y);
        }
        __syncthreads();
    }

    // Final forward h pair is in sh_h[0] (step 1023 wrote buffer (1024&1)=0).
    // Backward direction contributes only its FIRST step (h0=c0=0):
    //   z = xprojB(x[T-1]);  c = i*g;  h_b = o*tanh(c);  masked -> 0 if !m.
    if (t < UU) {
        const int2 tkL = sh_tok[TT - 1];

        float hb0, hb1;
        {
            int tok = tkL.x;
            float ii = sigmoid_fast(g_xprojB[tok][t]);
            float gg = tanh_fast(g_xprojB[tok][2 * UU + t]);
            float oo = sigmoid_fast(g_xprojB[tok][3 * UU + t]);
            hb0 = sh_mask[tok] ? oo * tanh_fast(ii * gg) : 0.f;
        }
        {
            int tok = tkL.y;
            float ii = sigmoid_fast(g_xprojB[tok][t]);
            float gg = tanh_fast(g_xprojB[tok][2 * UU + t]);
            float oo = sigmoid_fast(g_xprojB[tok][3 * UU + t]);
            hb1 = sh_mask[tok] ? oo * tanh_fast(ii * gg) : 0.f;
        }

        const float2 hF = sh_h[0][t];
        float c0 = hF.x * Wd[t] + hb0 * Wd[UU + t];
        float c1 = hF.y * Wd[t] + hb1 * Wd[UU + t];
        #pragma unroll
        for (int off = 16; off > 0; off >>= 1) {
            c0 += __shfl_down_sync(0xffffffffu, c0, off);
            c1 += __shfl_down_sync(0xffffffffu, c1, off);
        }
        if (lane == 0) {
            sh_red[(t >> 5) * 2 + 0] = c0;
            sh_red[(t >> 5) * 2 + 1] = c1;
        }
    }
    __syncthreads();
    if (t == 0) {
        out[b0] = sh_red[0] + sh_red[2] + bd[0];
        out[b1] = sh_red[1] + sh_red[3] + bd[0];
    }
}

// Input order (metadata): tokens, emb, Wk_f, Wr_f, b_f, Wk_b, Wr_b, b_b, Wd, bd
extern "C" void kernel_launch(void* const* d_in, const int* in_sizes, int n_in,
                              void* d_out, int out_size) {
    const int*   tokens = (const int*)  d_in[0];
    const float* emb    = (const float*)d_in[1];
    const float* Wk_f   = (const float*)d_in[2];
    const float* Wr_f   = (const float*)d_in[3];
    const float* b_f    = (const float*)d_in[4];
    const float* Wk_b   = (const float*)d_in[5];
    // d_in[6] = Wr_b: provably unused (backward recurrence collapses to step 1 from h0=0)
    const float* b_b    = (const float*)d_in[7];
    const float* Wd     = (const float*)d_in[8];
    const float* bd     = (const float*)d_in[9];
    float*       out    = (float*)d_out;

    precompute_kernel<<<VV, GG>>>(emb, Wk_f, b_f, Wk_b, b_b);
    lstm_fwd2_kernel<<<BB / 2, 256>>>(tokens, Wr_f, Wd, bd, out);
}

// round 4
// speedup vs baseline: 1.1233x; 1.1233x over previous
#include <cuda_runtime.h>

// Problem constants
#define BB 256
#define TT 1024
#define VV 6
#define DD 64
#define UU 64
#define GG 256   // 4*U gate columns

// Precomputed per-vocab tables (V=6).
// Forward table is PERMUTED: index p = u*4+gi holds column col = gi*64+u,
// so thread l (u=l>>2, gi=l&3) reads index l -> stride-1, conflict-free.
__device__ float g_xprojF[VV][GG];
__device__ float g_xprojB[VV][GG];   // unpermuted (epilogue indexes by gate)
__device__ int   g_maskv[VV];

__device__ __forceinline__ float sigmoid_fast(float x) {
    return __fdividef(1.f, 1.f + __expf(-x));
}
__device__ __forceinline__ float tanh_fast(float x) {
    return 2.f * __fdividef(1.f, 1.f + __expf(-2.f * x)) - 1.f;
}

__device__ __forceinline__ unsigned long long pack2(float lo, float hi) {
    unsigned long long r;
    asm("mov.b64 %0, {%1, %2};" : "=l"(r) : "f"(lo), "f"(hi));
    return r;
}
__device__ __forceinline__ void unpack2(unsigned long long v, float& lo, float& hi) {
    asm("mov.b64 {%0, %1}, %2;" : "=f"(lo), "=f"(hi) : "l"(v));
}
// Packed dual-FMA: lanes {lo,hi} independently (sm_10x FFMA2 path)
#define FMA2(d, a, b, c) \
    asm("fma.rn.f32x2 %0, %1, %2, %3;" : "=l"(d) : "l"(a), "l"(b), "l"(c))
#define ADD2(d, a, b) \
    asm("add.rn.f32x2 %0, %1, %2;" : "=l"(d) : "l"(a), "l"(b))

__global__ void precompute_kernel(const float* __restrict__ emb,
                                  const float* __restrict__ Wk_f,
                                  const float* __restrict__ b_f,
                                  const float* __restrict__ Wk_b,
                                  const float* __restrict__ b_b) {
    int v = blockIdx.x;
    int g = threadIdx.x;          // original gate column
    float sf = 0.f, sb = 0.f;
    #pragma unroll 8
    for (int k = 0; k < DD; k++) {
        float e = emb[v * DD + k];
        sf = fmaf(e, Wk_f[k * GG + g], sf);
        sb = fmaf(e, Wk_b[k * GG + g], sb);
    }
    int p = (g & 63) * 4 + (g >> 6);     // permuted slot for forward table
    g_xprojF[v][p] = sf + b_f[g];
    g_xprojB[v][g] = sb + b_b[g];
    if (g == 0) {
        int m = 0;
        for (int k = 0; k < DD; k++) m |= (emb[v * DD + k] != 0.f);
        g_maskv[v] = m;
    }
}

// Grid 128 CTAs x 512 threads (single wave, 1 CTA/SM, 4 warps/SMSP).
// Each CTA = 2 independent batch halves of 256 threads. Thread l of a half
// owns gate column col = gi*64+u (u=l>>2, gi=l&3). Matvec uses k-paired
// fma.rn.f32x2: 32 FMA2/thread, weights as 32 b64 pairs (64 regs).
// h double-buffered per half; per-half named barriers (ids 1,2).
__global__ void __launch_bounds__(512, 1)
lstm_fwd_kernel(const int* __restrict__ tokens,
                const float* __restrict__ Wr_f,
                const float* __restrict__ Wd,
                const float* __restrict__ bd,
                float* __restrict__ out) {
    __shared__ float sh_xF[VV * GG];                 // 6 KB (permuted layout)
    __shared__ int   sh_tok[2][TT];                  // 8 KB
    __shared__ __align__(16) float sh_h[2][2][UU];   // [half][buf][unit]
    __shared__ int   sh_mask[VV];
    __shared__ float sh_red[2][2];

    const int tid  = threadIdx.x;
    const int half = tid >> 8;           // 0 or 1
    const int l    = tid & 255;          // local id within half
    const int b    = blockIdx.x * 2 + half;
    const int u    = l >> 2;
    const int gi   = l & 3;
    const int col  = gi * UU + u;
    const int lane = tid & 31;
    const int qb   = lane & ~3;          // quad base lane
    const int barid = 1 + half;

    // Recurrent weight column as k-pairs: w2[j] = {Wr[2j][col], Wr[2j+1][col]}.
    unsigned long long w2[32];
    #pragma unroll
    for (int j = 0; j < 32; j++)
        w2[j] = pack2(Wr_f[(2 * j) * GG + col], Wr_f[(2 * j + 1) * GG + col]);

    // Stage tokens (per half) and tables (whole CTA).
    for (int i = l; i < TT; i += 256) sh_tok[half][i] = tokens[b * TT + i];
    for (int i = tid; i < VV * GG; i += 512) sh_xF[i] = (&g_xprojF[0][0])[i];
    if (tid < VV) sh_mask[tid] = g_maskv[tid];
    if (l < UU) { sh_h[half][0][l] = 0.f; sh_h[half][1][l] = 0.f; }
    __syncthreads();

    const int* __restrict__ tokp = sh_tok[half];
    float c = 0.f;   // cell state, live in gi==3 lanes

#define STEP(HR, HW, S) do {                                                   \
    const int tok = tokp[(S)];                                                 \
    /* seed acc0.lo with xproj (permuted table: index l), acc0.hi with 0 */    \
    unsigned long long a0 = pack2(sh_xF[tok * GG + l], 0.f);                   \
    unsigned long long a1 = 0ull, a2 = 0ull, a3 = 0ull;                        \
    const ulonglong2* __restrict__ hp = (const ulonglong2*)(HR);               \
    _Pragma("unroll")                                                          \
    for (int i = 0; i < 16; i += 2) {                                          \
        ulonglong2 pA = hp[i];          /* {h4i,h4i+1},{h4i+2,h4i+3} */        \
        ulonglong2 pB = hp[i + 1];                                             \
        FMA2(a0, pA.x, w2[2 * i + 0], a0);                                     \
        FMA2(a1, pA.y, w2[2 * i + 1], a1);                                     \
        FMA2(a2, pB.x, w2[2 * i + 2], a2);                                     \
        FMA2(a3, pB.y, w2[2 * i + 3], a3);                                     \
    }                                                                          \
    ADD2(a0, a0, a1); ADD2(a2, a2, a3); ADD2(a0, a0, a2);                      \
    float zlo, zhi; unpack2(a0, zlo, zhi);                                     \
    float z = zlo + zhi;                                                       \
    float a = (gi == 2) ? tanh_fast(z) : sigmoid_fast(z);                      \
    float vi = __shfl_sync(0xffffffffu, a, qb + 0);                            \
    float vf = __shfl_sync(0xffffffffu, a, qb + 1);                            \
    float vg = __shfl_sync(0xffffffffu, a, qb + 2);                            \
    if (gi == 3) {                                                             \
        float cn = fmaf(vf, c, vi * vg);                                       \
        float hn = a * tanh_fast(cn);                                          \
        int   m  = sh_mask[tok];                                               \
        float ho = (HR)[u];                                                    \
        c        = m ? cn : c;                                                 \
        (HW)[u]  = m ? hn : ho;                                                \
    }                                                                          \
    asm volatile("bar.sync %0, 256;" :: "r"(barid) : "memory");                \
} while (0)

    float* __restrict__ h0 = sh_h[half][0];
    float* __restrict__ h1 = sh_h[half][1];
    for (int s = 0; s < TT; s += 2) {
        STEP(h0, h1, s);
        STEP(h1, h0, s + 1);
    }
#undef STEP

    // Final forward h is in buf 0 (step 1023 wrote h0).
    // Backward direction = its first step only (h0=c0=0): z = xprojB(x[T-1]),
    // c = i*g, h_b = o*tanh(c), masked -> 0.
    if (l < UU) {
        const int tokL = tokp[TT - 1];
        float ii = sigmoid_fast(g_xprojB[tokL][l]);
        float gg = tanh_fast  (g_xprojB[tokL][2 * UU + l]);
        float oo = sigmoid_fast(g_xprojB[tokL][3 * UU + l]);
        float hb = sh_mask[tokL] ? oo * tanh_fast(ii * gg) : 0.f;

        float contrib = sh_h[half][0][l] * Wd[l] + hb * Wd[UU + l];
        #pragma unroll
        for (int off = 16; off > 0; off >>= 1)
            contrib += __shfl_down_sync(0xffffffffu, contrib, off);
        if (lane == 0) sh_red[half][l >> 5] = contrib;
    }
    asm volatile("bar.sync %0, 256;" :: "r"(barid) : "memory");
    if (l == 0) out[b] = sh_red[half][0] + sh_red[half][1] + bd[0];
}

// Input order (metadata): tokens, emb, Wk_f, Wr_f, b_f, Wk_b, Wr_b, b_b, Wd, bd
extern "C" void kernel_launch(void* const* d_in, const int* in_sizes, int n_in,
                              void* d_out, int out_size) {
    const int*   tokens = (const int*)  d_in[0];
    const float* emb    = (const float*)d_in[1];
    const float* Wk_f   = (const float*)d_in[2];
    const float* Wr_f   = (const float*)d_in[3];
    const float* b_f    = (const float*)d_in[4];
    const float* Wk_b   = (const float*)d_in[5];
    // d_in[6] = Wr_b: unused (backward recurrence collapses to step 1 from h0=0)
    const float* b_b    = (const float*)d_in[7];
    const float* Wd     = (const float*)d_in[8];
    const float* bd     = (const float*)d_in[9];
    float*       out    = (float*)d_out;

    precompute_kernel<<<VV, GG>>>(emb, Wk_f, b_f, Wk_b, b_b);
    lstm_fwd_kernel<<<BB / 2, 512>>>(tokens, Wr_f, Wd, bd, out);
}

// round 6
// speedup vs baseline: 1.2502x; 1.1130x over previous
#include <cuda_runtime.h>

// Problem constants
#define BB 256
#define TT 1024
#define VV 6
#define DD 64
#define UU 64
#define GG 256   // 4*U gate columns

// Precomputed per-vocab tables (V=6).
// Forward table PERMUTED for the 128-thread/batch mapping: thread l (u=l>>1,
// p=l&1) owns cols {p*64+u, 128+p*64+u} and reads slots {2l, 2l+1} as LDS.64.
// Original col g (gi=g>>6, u=g&63) -> slot 4u + 2*(gi&1) + (gi>>1).
__device__ float g_xprojF[VV][GG];
__device__ float g_xprojB[VV][GG];   // unpermuted (epilogue indexes by gate)
__device__ int   g_maskv[VV];

__device__ __forceinline__ float sigmoid_fast(float x) {
    return __fdividef(1.f, 1.f + __expf(-x));
}
__device__ __forceinline__ float tanh_fast(float x) {
    return 2.f * __fdividef(1.f, 1.f + __expf(-2.f * x)) - 1.f;
}

__device__ __forceinline__ unsigned long long pack2(float lo, float hi) {
    unsigned long long r;
    asm("mov.b64 %0, {%1, %2};" : "=l"(r) : "f"(lo), "f"(hi));
    return r;
}
__device__ __forceinline__ void unpack2(unsigned long long v, float& lo, float& hi) {
    asm("mov.b64 {%0, %1}, %2;" : "=f"(lo), "=f"(hi) : "l"(v));
}
// Packed dual-FMA: lanes {lo,hi} independently (sm_10x FFMA2 path)
#define FMA2(d, a, b, c) \
    asm("fma.rn.f32x2 %0, %1, %2, %3;" : "=l"(d) : "l"(a), "l"(b), "l"(c))
#define ADD2(d, a, b) \
    asm("add.rn.f32x2 %0, %1, %2;" : "=l"(d) : "l"(a), "l"(b))

__global__ void precompute_kernel(const float* __restrict__ emb,
                                  const float* __restrict__ Wk_f,
                                  const float* __restrict__ b_f,
                                  const float* __restrict__ Wk_b,
                                  const float* __restrict__ b_b) {
    int v = blockIdx.x;
    int g = threadIdx.x;          // original gate column
    float sf = 0.f, sb = 0.f;
    #pragma unroll 8
    for (int k = 0; k < DD; k++) {
        float e = emb[v * DD + k];
        sf = fmaf(e, Wk_f[k * GG + g], sf);
        sb = fmaf(e, Wk_b[k * GG + g], sb);
    }
    int u = g & 63, gi = g >> 6;
    int slot = 4 * u + 2 * (gi & 1) + (gi >> 1);
    g_xprojF[v][slot] = sf + b_f[g];
    g_xprojB[v][g]    = sb + b_b[g];
    if (g == 0) {
        int m = 0;
        for (int k = 0; k < DD; k++) m |= (emb[v * DD + k] != 0.f);
        g_maskv[v] = m;
    }
}

// Grid 128 CTAs x 256 threads: exactly 1 CTA/SM (uniform), 8 warps/SM =
// 2 warps/SMSP, the two warps on each SMSP belonging to INDEPENDENT halves.
// Each half = 128 threads = one batch. Thread l: u = l>>1, p = l&1;
// A (p=0) owns cols {u (i), 128+u (g)}; B (p=1) owns {64+u (f), 192+u (o)}.
// Matvec: 64 FMA2/thread (k-paired), h read as broadcast LDS.128.
// A sends sigmoid(i)*tanh(g) to B via one shfl_xor; B updates c,h locally.
__global__ void __launch_bounds__(256, 1)
lstm_fwd_kernel(const int* __restrict__ tokens,
                const float* __restrict__ Wr_f,
                const float* __restrict__ Wd,
                const float* __restrict__ bd,
                float* __restrict__ out) {
    __shared__ float sh_xF[VV * GG];                 // 6 KB (permuted)
    __shared__ int   sh_tok[2][TT];                  // 8 KB
    __shared__ __align__(16) float sh_h[2][2][UU];   // [half][buf][unit]
    __shared__ int   sh_mask[VV];
    __shared__ float sh_red[2][2];

    const int tid  = threadIdx.x;
    const int half = tid >> 7;           // 0 or 1
    const int l    = tid & 127;          // local id within half
    const int b    = blockIdx.x * 2 + half;
    const int u    = l >> 1;
    const int p    = l & 1;              // 0 = A{i,g}, 1 = B{f,o}
    const int colA = p * UU + u;         // i or f
    const int colB = 2 * UU + p * UU + u;// g or o
    const int lane = tid & 31;
    const int barid = 1 + half;

    // Recurrent weight columns as k-pairs: w[j] = {Wr[2j][col], Wr[2j+1][col]}.
    unsigned long long wA[32], wB[32];
    #pragma unroll
    for (int j = 0; j < 32; j++) {
        wA[j] = pack2(Wr_f[(2 * j) * GG + colA], Wr_f[(2 * j + 1) * GG + colA]);
        wB[j] = pack2(Wr_f[(2 * j) * GG + colB], Wr_f[(2 * j + 1) * GG + colB]);
    }

    // Stage tokens (per half) and tables (whole CTA).
    for (int i = l; i < TT; i += 128) sh_tok[half][i] = tokens[b * TT + i];
    for (int i = tid; i < VV * GG; i += 256) sh_xF[i] = (&g_xprojF[0][0])[i];
    if (tid < VV) sh_mask[tid] = g_maskv[tid];
    if (l < UU) { sh_h[half][0][l] = 0.f; sh_h[half][1][l] = 0.f; }
    __syncthreads();

    const int* __restrict__ tokp = sh_tok[half];
    float c = 0.f;       // cell state (live in B threads)
    float hprev = 0.f;   // previous h for this unit (live in B threads)

#define STEP(HR, HW, S) do {                                                   \
    const int tok = tokp[(S)];                                                 \
    const float2 seed = *(const float2*)&sh_xF[tok * GG + 2 * l];              \
    unsigned long long aA0 = 0ull, aA1 = 0ull, aA2 = 0ull, aA3 = 0ull;         \
    unsigned long long aB0 = 0ull, aB1 = 0ull, aB2 = 0ull, aB3 = 0ull;         \
    const ulonglong2* __restrict__ hp = (const ulonglong2*)(HR);               \
    _Pragma("unroll")                                                          \
    for (int i = 0; i < 16; i += 2) {                                          \
        ulonglong2 pX = hp[i];       /* {h4i,h4i+1},{h4i+2,h4i+3} */           \
        ulonglong2 pY = hp[i + 1];                                             \
        FMA2(aA0, pX.x, wA[2 * i + 0], aA0);                                   \
        FMA2(aB0, pX.x, wB[2 * i + 0], aB0);                                   \
        FMA2(aA1, pX.y, wA[2 * i + 1], aA1);                                   \
        FMA2(aB1, pX.y, wB[2 * i + 1], aB1);                                   \
        FMA2(aA2, pY.x, wA[2 * i + 2], aA2);                                   \
        FMA2(aB2, pY.x, wB[2 * i + 2], aB2);                                   \
        FMA2(aA3, pY.y, wA[2 * i + 3], aA3);                                   \
        FMA2(aB3, pY.y, wB[2 * i + 3], aB3);                                   \
    }                                                                          \
    ADD2(aA0, aA0, aA1); ADD2(aA2, aA2, aA3); ADD2(aA0, aA0, aA2);             \
    ADD2(aB0, aB0, aB1); ADD2(aB2, aB2, aB3); ADD2(aB0, aB0, aB2);             \
    float zAl, zAh, zBl, zBh;                                                  \
    unpack2(aA0, zAl, zAh); unpack2(aB0, zBl, zBh);                            \
    float zA = zAl + zAh + seed.x;   /* i or f */                              \
    float zB = zBl + zBh + seed.y;   /* g or o */                              \
    float actA = sigmoid_fast(zA);                                             \
    float actB = (p == 0) ? tanh_fast(zB) : sigmoid_fast(zB);                  \
    float sendv = actA * actB;       /* A: i*g ; B: unused */                  \
    float ig = __shfl_xor_sync(0xffffffffu, sendv, 1);                         \
    if (p == 1) {                                                              \
        float cn = fmaf(actA, c, ig);        /* f*c + i*g */                   \
        float hn = actB * tanh_fast(cn);     /* o * tanh(c) */                 \
        int   m  = sh_mask[tok];                                               \
        c     = m ? cn : c;                                                    \
        hprev = m ? hn : hprev;                                                \
        (HW)[u] = hprev;                                                       \
    }                                                                          \
    asm volatile("bar.sync %0, 128;" :: "r"(barid) : "memory");                \
} while (0)

    float* __restrict__ h0 = sh_h[half][0];
    float* __restrict__ h1 = sh_h[half][1];
    for (int s = 0; s < TT; s += 2) {
        STEP(h0, h1, s);
        STEP(h1, h0, s + 1);
    }
#undef STEP

    // Final forward h is in buf 0 (step 1023 wrote h0).
    // Backward direction = its first step only (h0=c0=0): z = xprojB(x[T-1]),
    // c = i*g, h_b = o*tanh(c), masked -> 0.
    if (l < UU) {
        const int tokL = tokp[TT - 1];
        float ii = sigmoid_fast(g_xprojB[tokL][l]);
        float gg = tanh_fast  (g_xprojB[tokL][2 * UU + l]);
        float oo = sigmoid_fast(g_xprojB[tokL][3 * UU + l]);
        float hb = sh_mask[tokL] ? oo * tanh_fast(ii * gg) : 0.f;

        float contrib = sh_h[half][0][l] * Wd[l] + hb * Wd[UU + l];
        #pragma unroll
        for (int off = 16; off > 0; off >>= 1)
            contrib += __shfl_down_sync(0xffffffffu, contrib, off);
        if (lane == 0) sh_red[half][l >> 5] = contrib;
    }
    asm volatile("bar.sync %0, 128;" :: "r"(barid) : "memory");
    if (l == 0) out[b] = sh_red[half][0] + sh_red[half][1] + bd[0];
}

// Input order (metadata): tokens, emb, Wk_f, Wr_f, b_f, Wk_b, Wr_b, b_b, Wd, bd
extern "C" void kernel_launch(void* const* d_in, const int* in_sizes, int n_in,
                              void* d_out, int out_size) {
    const int*   tokens = (const int*)  d_in[0];
    const float* emb    = (const float*)d_in[1];
    const float* Wk_f   = (const float*)d_in[2];
    const float* Wr_f   = (const float*)d_in[3];
    const float* b_f    = (const float*)d_in[4];
    const float* Wk_b   = (const float*)d_in[5];
    // d_in[6] = Wr_b: unused (backward recurrence collapses to step 1 from h0=0)
    const float* b_b    = (const float*)d_in[7];
    const float* Wd     = (const float*)d_in[8];
    const float* bd     = (const float*)d_in[9];
    float*       out    = (float*)d_out;

    precompute_kernel<<<VV, GG>>>(emb, Wk_f, b_f, Wk_b, b_b);
    lstm_fwd_kernel<<<BB / 2, 256>>>(tokens, Wr_f, Wd, bd, out);
}